// round 9
// baseline (speedup 1.0000x reference)
#include <cuda_runtime.h>
#include <cuda_bf16.h>
#include <cstdint>

// YOLO layer: (B, 3*85, 76, 76) fp32 -> (B, 3*76*76, 85) fp32
// HBM-bound transpose + elementwise epilogue.
//
// Per CTA: one EVEN ROW-PAIR (2t, 2t+1) of one (batch, anchor):
//   - per channel, the two rows are CONTIGUOUS: 608B starting 32B-aligned
//     (2t*304 % 32 == 0) -> exactly 19 sectors read, 0% amplification.
//   - output block (152 x 85 floats = 51680B) is contiguous -> smem tile in
//     output order, stored via 5 parallel cp.async.bulk chunks of 10336B
//     (646 vec4 each; 3230 = 5*646, 10336 % 16 == 0).
//   phase 1: each thread front-batches its 4 vec4 LDGs (high MLP)
//   phase 2: transform + smem scatter (stride 85)
// TPB=1024, __launch_bounds__(1024,2) pins regs<=32 -> 2 CTAs/SM = 2048 thr/SM.

#define G     76
#define C     85
#define NA    3
#define TPB   1024
#define HP    (G / 2)          // 38 row-pairs
#define TILE  (C * 2 * G)      // 12920 floats (51680 B)
#define TILE4 (TILE / 4)       // 3230 vec4
#define VPC2  (2 * G / 4)      // 38 vec4 per channel (both rows)
#define NIT   4                // 1024*4 = 4096 >= 3230
#define NCHUNK 5
#define CHUNK4 (TILE4 / NCHUNK)     // 646 vec4
#define CHUNKB (CHUNK4 * 16)        // 10336 B (16B multiple)

__device__ __forceinline__ float sigf(float v) {
    return __fdividef(1.0f, 1.0f + __expf(-v));
}

__global__ __launch_bounds__(TPB, 2)
void yolo_kernel(const float* __restrict__ in,
                 const void*  __restrict__ imgdim_p,
                 float* __restrict__ out)
{
    __shared__ __align__(16) float tile[TILE];

    const int blk = blockIdx.x;
    const int tp  = blk % HP;             // row pair index
    const int a   = (blk / HP) % NA;      // anchor
    const int b   = blk / (HP * NA);      // batch
    const int t0  = 2 * tp;               // first grid row (even)

    float stride = 8.0f;
    if (imgdim_p) {
        int iv = *(const int*)imgdim_p;
        float dim = (iv > 0 && iv < (1 << 20)) ? (float)iv : __int_as_float(iv);
        stride = dim / (float)G;
    }

    const float AW[NA] = {116.0f, 156.0f, 373.0f};
    const float AH[NA] = { 90.0f, 198.0f, 326.0f};
    const float aw = AW[a], ah = AH[a];

    // channel k occupies 608B contiguous: rows t0 and t0+1
    const float* base = in + ((size_t)(b * NA + a) * C) * (G * G) + (size_t)t0 * G;

    // ---- phase 1: front-batch all loads (4 independent LDG.128) ----
    float4 v[NIT];
    #pragma unroll
    for (int j = 0; j < NIT; j++) {
        const unsigned i = threadIdx.x + j * TPB;
        if (i < TILE4) {
            const unsigned k = i / VPC2;          // channel 0..84
            const unsigned q = i - k * VPC2;      // vec4 0..37 within 2-row strip
            v[j] = __ldcs((const float4*)(base + (size_t)k * (G * G)) + q);
        }
    }

    // ---- phase 2: transform + scatter to smem in output order ----
    #pragma unroll
    for (int j = 0; j < NIT; j++) {
        const unsigned i = threadIdx.x + j * TPB;
        if (i < TILE4) {
            const unsigned k = i / VPC2;
            const unsigned q = i - k * VPC2;
            const int s0  = q * 4;                // 0..148, never straddles 76
            const int row = (s0 >= G) ? 1 : 0;    // uniform per vec4
            const int gx0 = s0 - row * G;         // grid_x of component 0
            const float gy = (float)(t0 + row);
            const float4 w = v[j];

            float r0, r1, r2, r3;
            if (k >= 4) {
                r0 = sigf(w.x); r1 = sigf(w.y); r2 = sigf(w.z); r3 = sigf(w.w);
            } else if (k == 0) {
                r0 = (sigf(w.x) + (float)(gx0 + 0)) * stride;
                r1 = (sigf(w.y) + (float)(gx0 + 1)) * stride;
                r2 = (sigf(w.z) + (float)(gx0 + 2)) * stride;
                r3 = (sigf(w.w) + (float)(gx0 + 3)) * stride;
            } else if (k == 1) {
                r0 = (sigf(w.x) + gy) * stride;
                r1 = (sigf(w.y) + gy) * stride;
                r2 = (sigf(w.z) + gy) * stride;
                r3 = (sigf(w.w) + gy) * stride;
            } else if (k == 2) {
                r0 = __expf(w.x) * aw; r1 = __expf(w.y) * aw;
                r2 = __expf(w.z) * aw; r3 = __expf(w.w) * aw;
            } else {
                r0 = __expf(w.x) * ah; r1 = __expf(w.y) * ah;
                r2 = __expf(w.z) * ah; r3 = __expf(w.w) * ah;
            }
            float* p = &tile[(unsigned)s0 * C + k];
            p[0]     = r0;
            p[C]     = r1;
            p[2 * C] = r2;
            p[3 * C] = r3;
        }
    }
    __syncthreads();

    // ---- phase 3: 5 parallel bulk async stores (10336B each) ----
    {
        const int warp = threadIdx.x >> 5;
        const int lane = threadIdx.x & 31;
        if (warp < NCHUNK && lane == 0) {
            float* gdst = out +
                ((size_t)(b * NA + a) * (G * G) + (size_t)t0 * G) * C +
                (size_t)warp * (CHUNK4 * 4);
            const float* sbuf = tile + warp * (CHUNK4 * 4);
            uint32_t saddr;
            asm("{ .reg .u64 t0; cvta.to.shared.u64 t0, %1; cvt.u32.u64 %0, t0; }"
                : "=r"(saddr) : "l"(sbuf));
            asm volatile("fence.proxy.async.shared::cta;" ::: "memory");
            asm volatile("cp.async.bulk.global.shared::cta.bulk_group [%0], [%1], %2;"
                         :: "l"(gdst), "r"(saddr), "n"(CHUNKB) : "memory");
            asm volatile("cp.async.bulk.commit_group;" ::: "memory");
            asm volatile("cp.async.bulk.wait_group 0;" ::: "memory");
        }
    }
}

extern "C" void kernel_launch(void* const* d_in, const int* in_sizes, int n_in,
                              void* d_out, int out_size)
{
    const float* x = (const float*)d_in[0];
    const void*  dim = (n_in > 1) ? d_in[1] : nullptr;
    const int B = in_sizes[0] / (NA * C * G * G);   // 64 for the bench shape

    dim3 grid(B * NA * HP);
    yolo_kernel<<<grid, TPB>>>(x, dim, (float*)d_out);
}

// round 10
// speedup vs baseline: 1.0995x; 1.0995x over previous
#include <cuda_runtime.h>
#include <cuda_bf16.h>
#include <cstdint>

// YOLO layer: (B, 3*85, 76, 76) fp32 -> (B, 3*76*76, 85) fp32
// HBM-bound transpose + elementwise epilogue. Round-5 winning shape:
//   TPB=512, one (b,anchor,row) per CTA, NIT=4 front-batched vec4 LDGs,
//   transform + smem scatter (output order, stride 85).
// Deltas vs round 5:
//   - loads use default policy (__ldg): adjacent-row CTAs share boundary
//     32B sectors (304B rows, 16B aligned) -> keep them in L2.
//   - epilogue: 5 parallel cp.async.bulk chunks of 5168B (warps 0..4),
//     parallelizing the tail drain. Epilogue-only, no hot-loop reg cost.

#define G     76
#define C     85
#define NA    3
#define TPB   512
#define TILE  (C * G)         // 6460 floats (25840 B)
#define TILE4 (TILE / 4)      // 1615 vec4
#define VPC   (G / 4)         // 19 vec4 per channel row
#define NIT   4               // 512*4 = 2048 >= 1615
#define NCHUNK 5
#define CHUNK4 (TILE4 / NCHUNK)   // 323 vec4
#define CHUNKB (CHUNK4 * 16)      // 5168 B (16B multiple)

__device__ __forceinline__ float sigf(float v) {
    return __fdividef(1.0f, 1.0f + __expf(-v));
}

__global__ __launch_bounds__(TPB)
void yolo_kernel(const float* __restrict__ in,
                 const void*  __restrict__ imgdim_p,
                 float* __restrict__ out)
{
    __shared__ __align__(16) float tile[TILE];

    const int blk = blockIdx.x;
    const int t   = blk % G;              // grid row (grid_y)
    const int a   = (blk / G) % NA;       // anchor
    const int b   = blk / (G * NA);       // batch

    float stride = 8.0f;
    if (imgdim_p) {
        int iv = *(const int*)imgdim_p;
        float dim = (iv > 0 && iv < (1 << 20)) ? (float)iv : __int_as_float(iv);
        stride = dim / (float)G;
    }

    const float AW[NA] = {116.0f, 156.0f, 373.0f};
    const float AH[NA] = { 90.0f, 198.0f, 326.0f};
    const float aw = AW[a], ah = AH[a];
    const float gy = (float)t;

    const float* base = in + ((size_t)(b * NA + a) * C) * (G * G) + (size_t)t * G;

    // ---- phase 1: batch all loads (4 independent LDG.128 in flight) ----
    float4 v[NIT];
    #pragma unroll
    for (int j = 0; j < NIT; j++) {
        const unsigned i = threadIdx.x + j * TPB;
        if (i < TILE4) {
            const unsigned k = i / VPC;
            const unsigned q = i - k * VPC;
            v[j] = __ldg((const float4*)(base + (size_t)k * (G * G)) + q);
        }
    }

    // ---- phase 2: transform + scatter to smem in output order ----
    #pragma unroll
    for (int j = 0; j < NIT; j++) {
        const unsigned i = threadIdx.x + j * TPB;
        if (i < TILE4) {
            const unsigned k = i / VPC;        // channel 0..84
            const unsigned q = i - k * VPC;    // vec4 index 0..18
            const int s0 = q * 4;
            const float4 w = v[j];

            float r0, r1, r2, r3;
            if (k >= 4) {
                r0 = sigf(w.x); r1 = sigf(w.y); r2 = sigf(w.z); r3 = sigf(w.w);
            } else if (k == 0) {
                r0 = (sigf(w.x) + (float)(s0 + 0)) * stride;
                r1 = (sigf(w.y) + (float)(s0 + 1)) * stride;
                r2 = (sigf(w.z) + (float)(s0 + 2)) * stride;
                r3 = (sigf(w.w) + (float)(s0 + 3)) * stride;
            } else if (k == 1) {
                r0 = (sigf(w.x) + gy) * stride;
                r1 = (sigf(w.y) + gy) * stride;
                r2 = (sigf(w.z) + gy) * stride;
                r3 = (sigf(w.w) + gy) * stride;
            } else if (k == 2) {
                r0 = __expf(w.x) * aw; r1 = __expf(w.y) * aw;
                r2 = __expf(w.z) * aw; r3 = __expf(w.w) * aw;
            } else {
                r0 = __expf(w.x) * ah; r1 = __expf(w.y) * ah;
                r2 = __expf(w.z) * ah; r3 = __expf(w.w) * ah;
            }
            float* p = &tile[(unsigned)s0 * C + k];
            p[0]     = r0;
            p[C]     = r1;
            p[2 * C] = r2;
            p[3 * C] = r3;
        }
    }
    __syncthreads();

    // ---- phase 3: 5 parallel bulk async stores (5168B each) ----
    {
        const int warp = threadIdx.x >> 5;
        const int lane = threadIdx.x & 31;
        if (warp < NCHUNK && lane == 0) {
            float* gdst = out +
                ((size_t)(b * NA + a) * (G * G) + (size_t)t * G) * C +
                (size_t)warp * (CHUNK4 * 4);
            const float* sbuf = tile + warp * (CHUNK4 * 4);
            uint32_t saddr;
            asm("{ .reg .u64 t0; cvta.to.shared.u64 t0, %1; cvt.u32.u64 %0, t0; }"
                : "=r"(saddr) : "l"(sbuf));
            asm volatile("fence.proxy.async.shared::cta;" ::: "memory");
            asm volatile("cp.async.bulk.global.shared::cta.bulk_group [%0], [%1], %2;"
                         :: "l"(gdst), "r"(saddr), "n"(CHUNKB) : "memory");
            asm volatile("cp.async.bulk.commit_group;" ::: "memory");
            asm volatile("cp.async.bulk.wait_group 0;" ::: "memory");
        }
    }
}

extern "C" void kernel_launch(void* const* d_in, const int* in_sizes, int n_in,
                              void* d_out, int out_size)
{
    const float* x = (const float*)d_in[0];
    const void*  dim = (n_in > 1) ? d_in[1] : nullptr;
    const int B = in_sizes[0] / (NA * C * G * G);   // 64 for the bench shape

    dim3 grid(B * NA * G);
    yolo_kernel<<<grid, TPB>>>(x, dim, (float*)d_out);
}

// round 11
// speedup vs baseline: 1.1181x; 1.0169x over previous
#include <cuda_runtime.h>
#include <cuda_bf16.h>
#include <cstdint>

// YOLO layer: (B, 3*85, 76, 76) fp32 -> (B, 3*76*76, 85) fp32
// HBM-bound transpose + elementwise epilogue. Round-5 winning shape, exactly:
//   TPB=512, one (b,anchor,row) per CTA, 4 front-batched vec4 LDGs/thread,
//   transform + smem scatter (output order, stride 85), SINGLE thread-0
//   cp.async.bulk store (chunked variants cost +5 regs -> occupancy cliff).
// Only deltas vs round 5:
//   - __ldg (default policy) instead of __ldcs: adjacent-row CTAs share
//     boundary 32B sectors (304B rows, 16B-aligned) -> keep them in L2.
//   - __launch_bounds__(512,4): pin the 32-reg / 4-CTA-per-SM operating point.

#define G     76
#define C     85
#define NA    3
#define TPB   512
#define TILE  (C * G)         // 6460 floats (25840 B)
#define TILE4 (TILE / 4)      // 1615 vec4
#define VPC   (G / 4)         // 19 vec4 per channel row
#define NIT   4               // 512*4 = 2048 >= 1615

__device__ __forceinline__ float sigf(float v) {
    return __fdividef(1.0f, 1.0f + __expf(-v));
}

__global__ __launch_bounds__(TPB, 4)
void yolo_kernel(const float* __restrict__ in,
                 const void*  __restrict__ imgdim_p,
                 float* __restrict__ out)
{
    __shared__ __align__(16) float tile[TILE];

    const int blk = blockIdx.x;
    const int t   = blk % G;              // grid row (grid_y)
    const int a   = (blk / G) % NA;       // anchor
    const int b   = blk / (G * NA);       // batch

    float stride = 8.0f;
    if (imgdim_p) {
        int iv = *(const int*)imgdim_p;
        float dim = (iv > 0 && iv < (1 << 20)) ? (float)iv : __int_as_float(iv);
        stride = dim / (float)G;
    }

    const float AW[NA] = {116.0f, 156.0f, 373.0f};
    const float AH[NA] = { 90.0f, 198.0f, 326.0f};
    const float aw = AW[a], ah = AH[a];
    const float gy = (float)t;

    const float* base = in + ((size_t)(b * NA + a) * C) * (G * G) + (size_t)t * G;

    // ---- phase 1: batch all loads (4 independent LDG.128 in flight) ----
    float4 v[NIT];
    #pragma unroll
    for (int j = 0; j < NIT; j++) {
        const unsigned i = threadIdx.x + j * TPB;
        if (i < TILE4) {
            const unsigned k = i / VPC;
            const unsigned q = i - k * VPC;
            v[j] = __ldg((const float4*)(base + (size_t)k * (G * G)) + q);
        }
    }

    // ---- phase 2: transform + scatter to smem in output order ----
    #pragma unroll
    for (int j = 0; j < NIT; j++) {
        const unsigned i = threadIdx.x + j * TPB;
        if (i < TILE4) {
            const unsigned k = i / VPC;        // channel 0..84
            const unsigned q = i - k * VPC;    // vec4 index 0..18
            const int s0 = q * 4;
            const float4 w = v[j];

            float r0, r1, r2, r3;
            if (k >= 4) {
                r0 = sigf(w.x); r1 = sigf(w.y); r2 = sigf(w.z); r3 = sigf(w.w);
            } else if (k == 0) {
                r0 = (sigf(w.x) + (float)(s0 + 0)) * stride;
                r1 = (sigf(w.y) + (float)(s0 + 1)) * stride;
                r2 = (sigf(w.z) + (float)(s0 + 2)) * stride;
                r3 = (sigf(w.w) + (float)(s0 + 3)) * stride;
            } else if (k == 1) {
                r0 = (sigf(w.x) + gy) * stride;
                r1 = (sigf(w.y) + gy) * stride;
                r2 = (sigf(w.z) + gy) * stride;
                r3 = (sigf(w.w) + gy) * stride;
            } else if (k == 2) {
                r0 = __expf(w.x) * aw; r1 = __expf(w.y) * aw;
                r2 = __expf(w.z) * aw; r3 = __expf(w.w) * aw;
            } else {
                r0 = __expf(w.x) * ah; r1 = __expf(w.y) * ah;
                r2 = __expf(w.z) * ah; r3 = __expf(w.w) * ah;
            }
            float* p = &tile[(unsigned)s0 * C + k];
            p[0]     = r0;
            p[C]     = r1;
            p[2 * C] = r2;
            p[3 * C] = r3;
        }
    }
    __syncthreads();

    // ---- phase 3: single bulk async store of the contiguous output block ----
    if (threadIdx.x == 0) {
        float* obase = out + ((size_t)(b * NA + a) * (G * G) + (size_t)t * G) * C;
        uint32_t saddr;
        asm("{ .reg .u64 t0; cvta.to.shared.u64 t0, %1; cvt.u32.u64 %0, t0; }"
            : "=r"(saddr) : "l"(tile));
        asm volatile("fence.proxy.async.shared::cta;" ::: "memory");
        asm volatile("cp.async.bulk.global.shared::cta.bulk_group [%0], [%1], %2;"
                     :: "l"(obase), "r"(saddr), "n"(TILE * 4) : "memory");
        asm volatile("cp.async.bulk.commit_group;" ::: "memory");
        asm volatile("cp.async.bulk.wait_group 0;" ::: "memory");
    }
}

extern "C" void kernel_launch(void* const* d_in, const int* in_sizes, int n_in,
                              void* d_out, int out_size)
{
    const float* x = (const float*)d_in[0];
    const void*  dim = (n_in > 1) ? d_in[1] : nullptr;
    const int B = in_sizes[0] / (NA * C * G * G);   // 64 for the bench shape

    dim3 grid(B * NA * G);
    yolo_kernel<<<grid, TPB>>>(x, dim, (float*)d_out);
}